// round 3
// baseline (speedup 1.0000x reference)
#include <cuda_runtime.h>

#define B    8
#define C    64
#define C3   192
#define Hdim 256
#define Wdim 256
#define HW   65536

// Scratch (device globals: allocation-free per harness rules)
__device__ float g_qkv [(size_t)B * C3 * HW];   // after 1x1 qkv conv
__device__ float g_qkvd[(size_t)B * C3 * HW];   // after 3x3 depthwise
__device__ float g_att [(size_t)B * C  * HW];   // after patch attention (pre-proj)

// ---------------------------------------------------------------------------
// K1: 1x1 conv  qkv[b,oc,px] = sum_ic w[oc,ic] * x[b,ic,px]
// grid: (B*1024 px-tiles of 64, 2 oc-halves of 96), 256 threads
// thread computes 3 oc x 8 px
// ---------------------------------------------------------------------------
__global__ __launch_bounds__(256) void k_qkv(const float* __restrict__ x,
                                             const float* __restrict__ w) {
    __shared__ float ws[96 * 65];   // padded stride 65 -> conflict-free broadcast
    __shared__ float xs[64 * 64];
    int b   = blockIdx.x >> 10;
    int px0 = (blockIdx.x & 1023) << 6;
    int ocH = blockIdx.y * 96;
    int t   = threadIdx.x;

    for (int i = t; i < 96 * 64; i += 256) {
        int r = i >> 6, ic = i & 63;
        ws[r * 65 + ic] = w[(ocH + r) * 64 + ic];
    }
    const float* xb = x + (size_t)b * C * HW + px0;
    for (int i = t; i < 64 * 16; i += 256) {
        int ic = i >> 4, p4 = i & 15;
        *(float4*)(xs + ic * 64 + p4 * 4) =
            *(const float4*)(xb + (size_t)ic * HW + p4 * 4);
    }
    __syncthreads();

    int pg  = (t & 7) * 8;      // 8 px
    int oc0 = (t >> 3) * 3;     // 3 oc within the 96-half
    float acc[3][8];
    #pragma unroll
    for (int r = 0; r < 3; r++)
        #pragma unroll
        for (int j = 0; j < 8; j++) acc[r][j] = 0.f;

    #pragma unroll 4
    for (int ic = 0; ic < 64; ic++) {
        float4 a0 = *(const float4*)(xs + ic * 64 + pg);
        float4 a1 = *(const float4*)(xs + ic * 64 + pg + 4);
        float xv[8] = {a0.x, a0.y, a0.z, a0.w, a1.x, a1.y, a1.z, a1.w};
        #pragma unroll
        for (int r = 0; r < 3; r++) {
            float wv = ws[(oc0 + r) * 65 + ic];
            #pragma unroll
            for (int j = 0; j < 8; j++) acc[r][j] += wv * xv[j];
        }
    }
    float* ob = g_qkv + (size_t)b * C3 * HW + px0 + pg;
    #pragma unroll
    for (int r = 0; r < 3; r++) {
        float* dst = ob + (size_t)(ocH + oc0 + r) * HW;
        *(float4*)dst       = make_float4(acc[r][0], acc[r][1], acc[r][2], acc[r][3]);
        *(float4*)(dst + 4) = make_float4(acc[r][4], acc[r][5], acc[r][6], acc[r][7]);
    }
}

// ---------------------------------------------------------------------------
// K2: 3x3 depthwise conv (cross-correlation, zero pad), per channel-plane
// grid: (W/32, H/8, B*C3), 256 threads (32x8 tile, halo 34x10)
// ---------------------------------------------------------------------------
__global__ __launch_bounds__(256) void k_dw(const float* __restrict__ dw) {
    __shared__ float sx[10][34];
    int plane = blockIdx.z;
    int ch    = plane % C3;
    int x0 = blockIdx.x * 32, y0 = blockIdx.y * 8;
    const float* ip = g_qkv + (size_t)plane * HW;
    int t  = threadIdx.x;
    int tx = t & 31, ty = t >> 5;

    for (int i = t; i < 340; i += 256) {
        int ly = i / 34, lx = i - ly * 34;
        int gy = y0 + ly - 1, gx = x0 + lx - 1;
        float v = 0.f;
        if ((unsigned)gy < (unsigned)Hdim && (unsigned)gx < (unsigned)Wdim)
            v = ip[gy * Wdim + gx];
        sx[ly][lx] = v;
    }
    __syncthreads();

    const float* wp = dw + ch * 9;
    float acc = 0.f;
    #pragma unroll
    for (int dy = 0; dy < 3; dy++)
        #pragma unroll
        for (int dx = 0; dx < 3; dx++)
            acc += wp[dy * 3 + dx] * sx[ty + dy][tx + dx];
    g_qkvd[(size_t)plane * HW + (size_t)(y0 + ty) * Wdim + (x0 + tx)] = acc;
}

// ---------------------------------------------------------------------------
// K3: per-patch circular convolution  out[i,j] = sum_{u,v} q[u,v]*k[(i-u)&7,(j-v)&7]
//     then *temperature[ch] * v  -> g_att
// grid: B*1024 (one block per (b,patch)), 512 threads: thread = (ch, row i)
// k staged in smem with channel-stride 72 + column XOR-row swizzle so the
// shifted-row scalar loads are bank-conflict-free across the warp.
// ---------------------------------------------------------------------------
__global__ __launch_bounds__(512) void k_attn(const float* __restrict__ temperature) {
    __shared__ float qs[64 * 65];
    __shared__ float ks[64 * 72];
    int b     = blockIdx.x >> 10;
    int patch = blockIdx.x & 1023;
    int py = patch >> 5, px = patch & 31;
    int t  = threadIdx.x;

    size_t base = (size_t)b * C3 * HW + (size_t)py * 8 * Wdim + px * 8;

    // load q (ch 0..63) and k (ch 64..127): 64ch x 8rows x 2 half-float4
    for (int i = t; i < 1024; i += 512) {
        int ch = i >> 4, rem = i & 15;
        int p1 = rem >> 1, hf = (rem & 1) * 4;
        const float* src = g_qkvd + base + (size_t)ch * HW + p1 * Wdim + hf;
        float4 qv = *(const float4*)src;
        float* qd = qs + ch * 65 + p1 * 8 + hf;
        qd[0] = qv.x; qd[1] = qv.y; qd[2] = qv.z; qd[3] = qv.w;
        float4 kv = *(const float4*)(src + (size_t)64 * HW);
        float* kd = ks + ch * 72 + p1 * 8;
        kd[(hf + 0) ^ p1] = kv.x;
        kd[(hf + 1) ^ p1] = kv.y;
        kd[(hf + 2) ^ p1] = kv.z;
        kd[(hf + 3) ^ p1] = kv.w;
    }
    __syncthreads();

    int ch = t >> 3, i = t & 7;
    float out[8];
    #pragma unroll
    for (int j = 0; j < 8; j++) out[j] = 0.f;

    const float* qb = qs + ch * 65;
    const float* kb = ks + ch * 72;
    #pragma unroll
    for (int u = 0; u < 8; u++) {
        int r = (i - u) & 7;
        float qr[8], kr[8];
        #pragma unroll
        for (int v = 0; v < 8; v++) qr[v] = qb[u * 8 + v];
        #pragma unroll
        for (int c2 = 0; c2 < 8; c2++) kr[c2] = kb[r * 8 + (c2 ^ r)];
        #pragma unroll
        for (int j = 0; j < 8; j++)
            #pragma unroll
            for (int v = 0; v < 8; v++)
                out[j] += qr[v] * kr[(j - v) & 7];
    }

    float tmp = __ldg(temperature + ch);
    const float* vrow = g_qkvd + base + (size_t)(128 + ch) * HW + i * Wdim;
    float4 v0 = *(const float4*)vrow;
    float4 v1 = *(const float4*)(vrow + 4);
    float* orow = g_att + (size_t)(b * C + ch) * HW
                + (size_t)(py * 8 + i) * Wdim + px * 8;
    *(float4*)orow       = make_float4(out[0]*tmp*v0.x, out[1]*tmp*v0.y,
                                       out[2]*tmp*v0.z, out[3]*tmp*v0.w);
    *(float4*)(orow + 4) = make_float4(out[4]*tmp*v1.x, out[5]*tmp*v1.y,
                                       out[6]*tmp*v1.z, out[7]*tmp*v1.w);
}

// ---------------------------------------------------------------------------
// K4: 1x1 proj  out[b,oc,px] = sum_ic pw[oc,ic] * g_att[b,ic,px]
// grid: B*1024 (64-px tiles), 256 threads; thread = 2 oc x 8 px
// ---------------------------------------------------------------------------
__global__ __launch_bounds__(256) void k_proj(const float* __restrict__ w,
                                              float* __restrict__ out) {
    __shared__ float ws[64 * 65];
    __shared__ float xs[64 * 64];
    int b   = blockIdx.x >> 10;
    int px0 = (blockIdx.x & 1023) << 6;
    int t   = threadIdx.x;

    for (int i = t; i < 64 * 64; i += 256) {
        int r = i >> 6, ic = i & 63;
        ws[r * 65 + ic] = w[i];
    }
    const float* xb = g_att + (size_t)b * C * HW + px0;
    for (int i = t; i < 64 * 16; i += 256) {
        int ic = i >> 4, p4 = i & 15;
        *(float4*)(xs + ic * 64 + p4 * 4) =
            *(const float4*)(xb + (size_t)ic * HW + p4 * 4);
    }
    __syncthreads();

    int pg  = (t & 7) * 8;
    int oc0 = (t >> 3) * 2;
    float acc[2][8];
    #pragma unroll
    for (int r = 0; r < 2; r++)
        #pragma unroll
        for (int j = 0; j < 8; j++) acc[r][j] = 0.f;

    #pragma unroll 4
    for (int ic = 0; ic < 64; ic++) {
        float4 a0 = *(const float4*)(xs + ic * 64 + pg);
        float4 a1 = *(const float4*)(xs + ic * 64 + pg + 4);
        float xv[8] = {a0.x, a0.y, a0.z, a0.w, a1.x, a1.y, a1.z, a1.w};
        #pragma unroll
        for (int r = 0; r < 2; r++) {
            float wv = ws[(oc0 + r) * 65 + ic];
            #pragma unroll
            for (int j = 0; j < 8; j++) acc[r][j] += wv * xv[j];
        }
    }
    float* ob = out + (size_t)b * C * HW + px0 + pg;
    #pragma unroll
    for (int r = 0; r < 2; r++) {
        float* dst = ob + (size_t)(oc0 + r) * HW;
        *(float4*)dst       = make_float4(acc[r][0], acc[r][1], acc[r][2], acc[r][3]);
        *(float4*)(dst + 4) = make_float4(acc[r][4], acc[r][5], acc[r][6], acc[r][7]);
    }
}

// ---------------------------------------------------------------------------
extern "C" void kernel_launch(void* const* d_in, const int* in_sizes, int n_in,
                              void* d_out, int out_size) {
    const float* x           = (const float*)d_in[0];
    const float* qkv_w       = (const float*)d_in[1];
    const float* dw_w        = (const float*)d_in[2];
    const float* proj_w      = (const float*)d_in[3];
    const float* temperature = (const float*)d_in[4];
    float* out = (float*)d_out;

    k_qkv <<<dim3(B * 1024, 2), 256>>>(x, qkv_w);
    k_dw  <<<dim3(Wdim / 32, Hdim / 8, B * C3), 256>>>(dw_w);
    k_attn<<<B * 1024, 512>>>(temperature);
    k_proj<<<B * 1024, 256>>>(proj_w, out);
}

// round 5
// speedup vs baseline: 1.4058x; 1.4058x over previous
#include <cuda_runtime.h>

#define B    8
#define C    64
#define C3   192
#define Hdim 256
#define Wdim 256
#define HW   65536

// Scratch (device globals: allocation-free per harness rules)
__device__ float g_qkv [(size_t)B * C3 * HW];   // after 1x1 qkv conv
__device__ float g_qkvd[(size_t)B * C3 * HW];   // after 3x3 depthwise
__device__ float g_att [(size_t)B * C  * HW];   // after patch attention (pre-proj)

// ---------------------------------------------------------------------------
// Register-blocked 1x1-conv GEMM core: 64 oc x 256 px tile, 256 threads,
// 8 oc x 8 px per thread, K=64 in two 32-row smem chunks.
// ws[oc][ic] read as warp-uniform scalar broadcasts (oc0 uniform per warp).
// xs float4 loads are lane-consecutive 16B -> conflict-free LDS.128.
// ---------------------------------------------------------------------------
__device__ __forceinline__ void gemm_64oc_256px(const float* __restrict__ in,
                                                const float* __restrict__ w,
                                                float* __restrict__ outp,
                                                int b, int px0, int ocH,
                                                size_t in_chanstride_total,
                                                size_t out_chanstride_total) {
    __shared__ float ws[64 * 64];    // 16 KB  [oc][ic]
    __shared__ float xs[32 * 256];   // 32 KB  [ic][px]
    int t = threadIdx.x;

    // weights: rows ocH..ocH+63, contiguous in global
    #pragma unroll
    for (int i = 0; i < 16; i++)
        ws[t + i * 256] = w[ocH * 64 + t + i * 256];

    int lane = t & 31;
    int pxA  = lane * 4;         // first half px group
    int oc0  = (t >> 5) * 8;     // warp-uniform

    float acc[8][8];
    #pragma unroll
    for (int r = 0; r < 8; r++)
        #pragma unroll
        for (int j = 0; j < 8; j++) acc[r][j] = 0.f;

    const float* xb = in + (size_t)b * in_chanstride_total + px0;

    for (int ckk = 0; ckk < 2; ckk++) {
        __syncthreads();
        // load xs: ic rows ckk*32 .. +32, 256 px each (8 float4 per thread)
        #pragma unroll
        for (int i = 0; i < 8; i++) {
            int idx = t + i * 256;           // 0..2047
            int ic  = idx >> 6;              // 0..31
            int p4  = idx & 63;              // float4 index in row
            *(float4*)(xs + ic * 256 + p4 * 4) =
                *(const float4*)(xb + (size_t)(ckk * 32 + ic) * HW + p4 * 4);
        }
        __syncthreads();

        #pragma unroll 4
        for (int ic = 0; ic < 32; ic++) {
            float4 a0 = *(const float4*)(xs + ic * 256 + pxA);
            float4 a1 = *(const float4*)(xs + ic * 256 + pxA + 128);
            float xv[8] = {a0.x, a0.y, a0.z, a0.w, a1.x, a1.y, a1.z, a1.w};
            int kk = ckk * 32 + ic;
            #pragma unroll
            for (int r = 0; r < 8; r++) {
                float wv = ws[(oc0 + r) * 64 + kk];
                #pragma unroll
                for (int j = 0; j < 8; j++) acc[r][j] += wv * xv[j];
            }
        }
    }

    float* ob = outp + (size_t)b * out_chanstride_total + px0;
    #pragma unroll
    for (int r = 0; r < 8; r++) {
        float* dst = ob + (size_t)(ocH + oc0 + r) * HW;
        *(float4*)(dst + pxA) =
            make_float4(acc[r][0], acc[r][1], acc[r][2], acc[r][3]);
        *(float4*)(dst + pxA + 128) =
            make_float4(acc[r][4], acc[r][5], acc[r][6], acc[r][7]);
    }
}

// K1: qkv 1x1: grid (B*256, 3), 256 threads
__global__ __launch_bounds__(256) void k_qkv(const float* __restrict__ x,
                                             const float* __restrict__ w) {
    int b   = blockIdx.x >> 8;
    int px0 = (blockIdx.x & 255) << 8;
    int ocH = blockIdx.y * 64;
    gemm_64oc_256px(x, w, g_qkv, b, px0, ocH,
                    (size_t)C * HW, (size_t)C3 * HW);
}

// K4: proj 1x1: grid B*256, 256 threads
__global__ __launch_bounds__(256) void k_proj(const float* __restrict__ w,
                                              float* __restrict__ out) {
    int b   = blockIdx.x >> 8;
    int px0 = (blockIdx.x & 255) << 8;
    gemm_64oc_256px(g_att, w, out, b, px0, 0,
                    (size_t)C * HW, (size_t)C * HW);
}

// ---------------------------------------------------------------------------
// K2: 3x3 depthwise conv (cross-correlation, zero pad), per channel-plane
// grid: (W/32, H/8, B*C3), 256 threads (32x8 tile, halo 34x10)
// ---------------------------------------------------------------------------
__global__ __launch_bounds__(256) void k_dw(const float* __restrict__ dw) {
    __shared__ float sx[10][34];
    int plane = blockIdx.z;
    int ch    = plane % C3;
    int x0 = blockIdx.x * 32, y0 = blockIdx.y * 8;
    const float* ip = g_qkv + (size_t)plane * HW;
    int t  = threadIdx.x;
    int tx = t & 31, ty = t >> 5;

    for (int i = t; i < 340; i += 256) {
        int ly = i / 34, lx = i - ly * 34;
        int gy = y0 + ly - 1, gx = x0 + lx - 1;
        float v = 0.f;
        if ((unsigned)gy < (unsigned)Hdim && (unsigned)gx < (unsigned)Wdim)
            v = ip[gy * Wdim + gx];
        sx[ly][lx] = v;
    }
    __syncthreads();

    const float* wp = dw + ch * 9;
    float acc = 0.f;
    #pragma unroll
    for (int dy = 0; dy < 3; dy++)
        #pragma unroll
        for (int dx = 0; dx < 3; dx++)
            acc += wp[dy * 3 + dx] * sx[ty + dy][tx + dx];
    g_qkvd[(size_t)plane * HW + (size_t)(y0 + ty) * Wdim + (x0 + tx)] = acc;
}

// ---------------------------------------------------------------------------
// K3: per-patch circular convolution  out[i,j] = sum_{u,v} q[u,v]*k[(i-u)&7,(j-v)&7]
//     then *temperature[ch] * v  -> g_att
// grid: B*1024 (one block per (b,patch)), 512 threads: thread = (ch, row i)
// q: stride-72, unswizzled -> 2 broadcast LDS.128 per u-step.
// k: stride-72 with column XOR-row swizzle -> conflict-free scalar loads.
// ---------------------------------------------------------------------------
__global__ __launch_bounds__(512) void k_attn(const float* __restrict__ temperature) {
    __shared__ float qs[64 * 72];
    __shared__ float ks[64 * 72];
    int b     = blockIdx.x >> 10;
    int patch = blockIdx.x & 1023;
    int py = patch >> 5, px = patch & 31;
    int t  = threadIdx.x;

    size_t base = (size_t)b * C3 * HW + (size_t)py * 8 * Wdim + px * 8;

    // load q (ch 0..63) and k (ch 64..127): 64ch x 8rows x 2 half-float4
    for (int i = t; i < 1024; i += 512) {
        int ch = i >> 4, rem = i & 15;
        int p1 = rem >> 1, hf = (rem & 1) * 4;
        const float* src = g_qkvd + base + (size_t)ch * HW + p1 * Wdim + hf;
        float4 qv = *(const float4*)src;
        *(float4*)(qs + ch * 72 + p1 * 8 + hf) = qv;
        float4 kv = *(const float4*)(src + (size_t)64 * HW);
        float* kd = ks + ch * 72 + p1 * 8;
        kd[(hf + 0) ^ p1] = kv.x;
        kd[(hf + 1) ^ p1] = kv.y;
        kd[(hf + 2) ^ p1] = kv.z;
        kd[(hf + 3) ^ p1] = kv.w;
    }
    __syncthreads();

    int ch = t >> 3, i = t & 7;
    float out[8];
    #pragma unroll
    for (int j = 0; j < 8; j++) out[j] = 0.f;

    const float* qb = qs + ch * 72;
    const float* kb = ks + ch * 72;
    #pragma unroll
    for (int u = 0; u < 8; u++) {
        int r = (i - u) & 7;
        float4 qa = *(const float4*)(qb + u * 8);
        float4 qc = *(const float4*)(qb + u * 8 + 4);
        float qr[8] = {qa.x, qa.y, qa.z, qa.w, qc.x, qc.y, qc.z, qc.w};
        float kr[8];
        #pragma unroll
        for (int c2 = 0; c2 < 8; c2++) kr[c2] = kb[r * 8 + (c2 ^ r)];
        #pragma unroll
        for (int j = 0; j < 8; j++)
            #pragma unroll
            for (int v = 0; v < 8; v++)
                out[j] += qr[v] * kr[(j - v) & 7];
    }

    float tmp = __ldg(temperature + ch);
    const float* vrow = g_qkvd + base + (size_t)(128 + ch) * HW + i * Wdim;
    float4 v0 = *(const float4*)vrow;
    float4 v1 = *(const float4*)(vrow + 4);
    float* orow = g_att + (size_t)(b * C + ch) * HW
                + (size_t)(py * 8 + i) * Wdim + px * 8;
    *(float4*)orow       = make_float4(out[0]*tmp*v0.x, out[1]*tmp*v0.y,
                                       out[2]*tmp*v0.z, out[3]*tmp*v0.w);
    *(float4*)(orow + 4) = make_float4(out[4]*tmp*v1.x, out[5]*tmp*v1.y,
                                       out[6]*tmp*v1.z, out[7]*tmp*v1.w);
}

// ---------------------------------------------------------------------------
extern "C" void kernel_launch(void* const* d_in, const int* in_sizes, int n_in,
                              void* d_out, int out_size) {
    const float* x           = (const float*)d_in[0];
    const float* qkv_w       = (const float*)d_in[1];
    const float* dw_w        = (const float*)d_in[2];
    const float* proj_w      = (const float*)d_in[3];
    const float* temperature = (const float*)d_in[4];
    float* out = (float*)d_out;

    k_qkv <<<dim3(B * 256, 3), 256>>>(x, qkv_w);
    k_dw  <<<dim3(Wdim / 32, Hdim / 8, B * C3), 256>>>(dw_w);
    k_attn<<<B * 1024, 512>>>(temperature);
    k_proj<<<B * 256, 256>>>(proj_w, out);
}